// round 11
// baseline (speedup 1.0000x reference)
#include <cuda_runtime.h>
#include <cstdint>
#include <cstddef>

// Adaptive separable convolution (SepConv), sm_103a.
// out[b,c,y,w] = sum_i sum_j inp[b,c,y+i,w+j] * V[b,i,y,w] * Hz[b,j,y,w]
//
// Round-11 = R10's ping-pong LDS pipeline at 4 CTAs/SM:
//  * FFMA2 (fma.rn.f32x2) packed math, 4 adjacent output pixels per thread,
//    one channel per CTA, TILE 128x4, 128-thread CTAs.
//  * 4 compile-time phases of 8/8/8/4 tap-pairs (byte bases 0/64/128/192,
//    16B-aligned -> dense conflict-free LDS.128).
//  * i-loop in steps of 2 with ping-pong qA/qB (row i+1 loads before row i's
//    FFMA2 block) -- the mechanism that raised issue/fma rates in R9/R10.
//  * register diet for __launch_bounds__(128, 4) -> 16 warps/SM:
//      - w[4][8]=64 regs reused per phase, qA/qB=32,
//      - o-accumulators carried PACKED across phases (no per-phase hadd),
//      - V loads placed for minimal liveness (2 live float4).

#define KF   51
#define BB   2
#define CC   3
#define HH   256
#define WW   256
#define HW   (HH * WW)            // 65536
#define IN_H (HH + KF - 1)        // 306
#define IN_W (WW + KF - 1)        // 306

#define TILE_W 128
#define TILE_H 4
#define PATCH_H (TILE_H + KF - 1) // 54
#define PATCH_W (TILE_W + KF - 1) // 178
#define PATCH_WP 180              // padded row: 720B; cols 178,179 zeroed
#define ROW_BYTES (PATCH_WP * 4)  // 720

#define NTHREADS 128              // 4 warps, one output row each

__device__ __forceinline__ uint64_t pk2(float lo, float hi) {
    uint64_t r;
    asm("mov.b64 %0, {%1,%2};" : "=l"(r) : "f"(lo), "f"(hi));
    return r;
}
__device__ __forceinline__ void ffma2(uint64_t& acc, uint64_t a, uint64_t b) {
    asm("fma.rn.f32x2 %0, %1, %2, %0;" : "+l"(acc) : "l"(a), "l"(b));
}
__device__ __forceinline__ float hadd2(uint64_t p) {
    float lo, hi;
    asm("mov.b64 {%0,%1}, %2;" : "=f"(lo), "=f"(hi) : "l"(p));
    return lo + hi;
}
__device__ __forceinline__ void lds128(uint64_t& q0, uint64_t& q1, uint32_t saddr) {
    asm("ld.shared.v2.u64 {%0,%1}, [%2];" : "=l"(q0), "=l"(q1) : "r"(saddr));
}

// One phase: tap-pairs m = MBASE .. MBASE+NP-1 (NP even, 8*MBASE % 16 == 0).
// Accumulates into packed o0..o3 (carried across phases by the caller).
template<int MBASE, int NP>
__device__ __forceinline__ void run_phase(
    const float* __restrict__ Hb, const float* __restrict__ Vb,
    uint32_t smbase,
    uint64_t& o0, uint64_t& o1, uint64_t& o2, uint64_t& o3)
{
    // packed weights: w[p][r] = (Hz[2m-p], Hz[2m+1-p]), m = MBASE + r.
    uint64_t w[4][NP];
#pragma unroll
    for (int p = 0; p < 4; ++p) {
#pragma unroll
        for (int r = 0; r < NP; ++r) {
            int m  = MBASE + r;
            int j0 = 2 * m - p;
            int j1 = j0 + 1;
            float f0 = (j0 >= 0 && j0 < KF) ? Hb[(size_t)j0 * HW + p] : 0.0f;
            float f1 = (j1 >= 0 && j1 < KF) ? Hb[(size_t)j1 * HW + p] : 0.0f;
            w[p][r] = pk2(f0, f1);
        }
    }

    const uint32_t sbase = smbase + (uint32_t)(8 * MBASE);
    uint64_t qA[NP], qB[NP];

    auto ldq = [&](uint64_t (&q)[NP], int row) {
        uint32_t a = sbase + (uint32_t)row * ROW_BYTES;
#pragma unroll
        for (int t = 0; t < NP / 2; ++t)
            lds128(q[2 * t], q[2 * t + 1], a + 16u * t);
    };
    auto comp = [&](const uint64_t (&q)[NP], float4 v) {
        uint64_t a0 = 0, a1 = 0, a2 = 0, a3 = 0;
#pragma unroll
        for (int r = 0; r < NP; ++r) {
            ffma2(a0, w[0][r], q[r]);
            ffma2(a1, w[1][r], q[r]);
            ffma2(a2, w[2][r], q[r]);
            ffma2(a3, w[3][r], q[r]);
        }
        ffma2(o0, pk2(v.x, v.x), a0);
        ffma2(o1, pk2(v.y, v.y), a1);
        ffma2(o2, pk2(v.z, v.z), a2);
        ffma2(o3, pk2(v.w, v.w), a3);
    };

    // software pipeline: load row i+1 / i+2 before consuming row i / i+1.
    // V liveness kept to 2: vn loaded just before comp(qA), next v4 just
    // before comp(qB).
    ldq(qA, 0);
    float4 v4 = *(const float4*)Vb;
    const float* Vp = Vb;
#pragma unroll 1
    for (int i = 0; i < KF - 1; i += 2) {      // i = 0,2,...,48
        ldq(qB, i + 1);
        float4 vn = *(const float4*)(Vp + HW);       // V row i+1
        comp(qA, v4);                          // row i
        ldq(qA, i + 2);                        // row i+2 <= 50 (in-bounds)
        float4 v2 = *(const float4*)(Vp + 2 * HW);   // V row i+2
        comp(qB, vn);                          // row i+1
        v4 = v2;
        Vp += 2 * HW;
    }
    comp(qA, v4);                              // row 50 (epilogue)
}

__global__ void __launch_bounds__(NTHREADS, 4)
sepconv_kernel(const float* __restrict__ inp,
               const float* __restrict__ ver,
               const float* __restrict__ hor,
               float* __restrict__ out)
{
    __shared__ __align__(16) float sm[PATCH_H][PATCH_WP];

    const int bx = blockIdx.x;            // 0..1   tile col
    const int by = blockIdx.y;            // 0..63  tile row
    const int bc = blockIdx.z;            // 0..5   (b, c) fused
    const int b  = bc / CC;
    const int c  = bc - b * CC;
    const int x0 = bx * TILE_W;
    const int y0 = by * TILE_H;

    const int tid  = threadIdx.x;
    const int lane = tid & 31;
    const int wy   = tid >> 5;            // warp id == row within tile
    const int y    = y0 + wy;             // output row
    const int w0   = x0 + 4 * lane;       // first of 4 output cols

    const float* Hb = hor + ((size_t)b * KF * HW) + (size_t)y * WW + w0;
    const float* Vb = ver + ((size_t)b * KF * HW) + (size_t)y * WW + w0;

    // ---- single patch fill for this CTA's channel (+ zero pad cols) ----
    {
        const float* src = inp + ((size_t)(b * CC + c) * IN_H + y0) * IN_W + x0;
        for (int t = tid; t < PATCH_H * (PATCH_W / 2); t += NTHREADS) {
            int r  = t / (PATCH_W / 2);
            int c2 = t - r * (PATCH_W / 2);
            float2 v = *(const float2*)(src + (size_t)r * IN_W + 2 * c2);
            *(float2*)(&sm[r][2 * c2]) = v;
        }
        if (tid < PATCH_H) {              // pad cols read by the dead pair m=27
            sm[tid][PATCH_W]     = 0.0f;
            sm[tid][PATCH_W + 1] = 0.0f;
        }
    }
    __syncthreads();

    // per-thread shared base address: row wy (+i), float col 4*lane
    const uint32_t smbase = (uint32_t)__cvta_generic_to_shared(&sm[0][0])
                          + (uint32_t)(wy * ROW_BYTES) + (uint32_t)(lane * 16);

    // packed accumulators, carried across all 4 phases
    uint64_t o0 = 0, o1 = 0, o2 = 0, o3 = 0;

    // phases: m = 0..7, 8..15, 16..23, 24..27 (byte bases 0/64/128/192)
    run_phase<0,  8>(Hb, Vb, smbase, o0, o1, o2, o3);
    __syncthreads();   // liveness fence: next phase's weights stay below
    run_phase<8,  8>(Hb, Vb, smbase, o0, o1, o2, o3);
    __syncthreads();
    run_phase<16, 8>(Hb, Vb, smbase, o0, o1, o2, o3);
    __syncthreads();
    run_phase<24, 4>(Hb, Vb, smbase, o0, o1, o2, o3);

    // ---- write out ----
    float* o = out + ((size_t)(b * CC + c) * HH + y) * WW + w0;
    *(float4*)o = make_float4(hadd2(o0), hadd2(o1), hadd2(o2), hadd2(o3));
}

extern "C" void kernel_launch(void* const* d_in, const int* in_sizes, int n_in,
                              void* d_out, int out_size)
{
    (void)in_sizes; (void)n_in; (void)out_size;
    const float* inp = (const float*)d_in[0];   // [B, C, 306, 306]
    const float* ver = (const float*)d_in[1];   // [B, 51, 256, 256]
    const float* hor = (const float*)d_in[2];   // [B, 51, 256, 256]
    float*       out = (float*)d_out;           // [B, C, 256, 256]

    dim3 grid(WW / TILE_W, HH / TILE_H, BB * CC);   // (2, 64, 6) = 768 blocks
    dim3 block(NTHREADS);
    sepconv_kernel<<<grid, block>>>(inp, ver, hor, out);
}

// round 12
// speedup vs baseline: 1.0825x; 1.0825x over previous
#include <cuda_runtime.h>
#include <cstdint>
#include <cstddef>

// Adaptive separable convolution (SepConv), sm_103a.
// out[b,c,y,w] = sum_i sum_j inp[b,c,y+i,w+j] * V[b,i,y,w] * Hz[b,j,y,w]
//
// Round-12 = R10 (3-phase ping-pong LDS pipeline, best issue/fma rates)
// + deep V prefetch:
//  * V circular register buffer of depth 4 (static slots, 4-rows-per-iter
//    loop): each V LDG issues ~4 comp blocks (~400-760cyc) before its use,
//    covering L2 (~250cyc) and first-wave DRAM (~577cyc) latency. All prior
//    kernels consumed V one block (~100-190cyc) after load -> ~400cyc/row
//    exposed stall, which matches the measured issue gap.
//  * packed o-accumulators carried across phases (pays the +16 V regs).
//  * FFMA2 packed math, 4 px/thread, 1 channel/CTA, TILE 128x4, 3 CTAs/SM.
//  * 3 compile-time phases of 10/10/8 tap-pairs (byte bases 0/80/160,
//    16B-aligned -> dense conflict-free LDS.128), ping-pong qA/qB.

#define KF   51
#define BB   2
#define CC   3
#define HH   256
#define WW   256
#define HW   (HH * WW)            // 65536
#define IN_H (HH + KF - 1)        // 306
#define IN_W (WW + KF - 1)        // 306

#define TILE_W 128
#define TILE_H 4
#define PATCH_H (TILE_H + KF - 1) // 54
#define PATCH_W (TILE_W + KF - 1) // 178
#define PATCH_WP 180              // padded row: 720B; cols 178,179 zeroed
#define ROW_BYTES (PATCH_WP * 4)  // 720

#define NTHREADS 128              // 4 warps, one output row each

__device__ __forceinline__ uint64_t pk2(float lo, float hi) {
    uint64_t r;
    asm("mov.b64 %0, {%1,%2};" : "=l"(r) : "f"(lo), "f"(hi));
    return r;
}
__device__ __forceinline__ void ffma2(uint64_t& acc, uint64_t a, uint64_t b) {
    asm("fma.rn.f32x2 %0, %1, %2, %0;" : "+l"(acc) : "l"(a), "l"(b));
}
__device__ __forceinline__ float hadd2(uint64_t p) {
    float lo, hi;
    asm("mov.b64 {%0,%1}, %2;" : "=f"(lo), "=f"(hi) : "l"(p));
    return lo + hi;
}
__device__ __forceinline__ void lds128(uint64_t& q0, uint64_t& q1, uint32_t saddr) {
    asm("ld.shared.v2.u64 {%0,%1}, [%2];" : "=l"(q0), "=l"(q1) : "r"(saddr));
}

// One phase: tap-pairs m = MBASE .. MBASE+NP-1 (NP even, 8*MBASE % 16 == 0).
// Accumulates into packed o0..o3 carried across phases.
template<int MBASE, int NP>
__device__ __forceinline__ void run_phase(
    const float* __restrict__ Hb, const float* __restrict__ Vb,
    uint32_t smbase,
    uint64_t& o0, uint64_t& o1, uint64_t& o2, uint64_t& o3)
{
    // packed weights: w[p][r] = (Hz[2m-p], Hz[2m+1-p]), m = MBASE + r.
    uint64_t w[4][NP];
#pragma unroll
    for (int p = 0; p < 4; ++p) {
#pragma unroll
        for (int r = 0; r < NP; ++r) {
            int m  = MBASE + r;
            int j0 = 2 * m - p;
            int j1 = j0 + 1;
            float f0 = (j0 >= 0 && j0 < KF) ? Hb[(size_t)j0 * HW + p] : 0.0f;
            float f1 = (j1 >= 0 && j1 < KF) ? Hb[(size_t)j1 * HW + p] : 0.0f;
            w[p][r] = pk2(f0, f1);
        }
    }

    const uint32_t sbase = smbase + (uint32_t)(8 * MBASE);
    uint64_t qA[NP], qB[NP];

    auto ldq = [&](uint64_t (&q)[NP], int row) {
        uint32_t a = sbase + (uint32_t)row * ROW_BYTES;
#pragma unroll
        for (int t = 0; t < NP / 2; ++t)
            lds128(q[2 * t], q[2 * t + 1], a + 16u * t);
    };
    auto ldv = [&](int row) -> float4 {
        return *(const float4*)(Vb + (size_t)row * HW);
    };
    auto comp = [&](const uint64_t (&q)[NP], float4 v) {
        uint64_t a0 = 0, a1 = 0, a2 = 0, a3 = 0;
#pragma unroll
        for (int r = 0; r < NP; ++r) {
            ffma2(a0, w[0][r], q[r]);
            ffma2(a1, w[1][r], q[r]);
            ffma2(a2, w[2][r], q[r]);
            ffma2(a3, w[3][r], q[r]);
        }
        ffma2(o0, pk2(v.x, v.x), a0);
        ffma2(o1, pk2(v.y, v.y), a1);
        ffma2(o2, pk2(v.z, v.z), a2);
        ffma2(o3, pk2(v.w, v.w), a3);
    };

    // prologue: LDS row 0, V rows 0..3 (depth-4 circular buffer, static slots)
    ldq(qA, 0);
    float4 v0 = ldv(0), v1 = ldv(1), v2 = ldv(2), v3 = ldv(3);

    // steady state: 4 rows per iteration, rows 0..47
#pragma unroll 1
    for (int i = 0; i < 48; i += 4) {
        ldq(qB, i + 1);
        comp(qA, v0); v0 = ldv(i + 4);
        ldq(qA, i + 2);
        comp(qB, v1); v1 = ldv(i + 5);
        ldq(qB, i + 3);
        comp(qA, v2); v2 = ldv(i + 6);
        ldq(qA, i + 4);
        comp(qB, v3); v3 = ldv(i + 7 < KF ? i + 7 : KF - 1);
    }
    // epilogue: rows 48, 49, 50 (qA holds row 48; v0,v1,v2 hold rows 48..50)
    ldq(qB, 49);
    comp(qA, v0);
    ldq(qA, 50);
    comp(qB, v1);
    comp(qA, v2);
}

__global__ void __launch_bounds__(NTHREADS, 3)
sepconv_kernel(const float* __restrict__ inp,
               const float* __restrict__ ver,
               const float* __restrict__ hor,
               float* __restrict__ out)
{
    __shared__ __align__(16) float sm[PATCH_H][PATCH_WP];

    const int bx = blockIdx.x;            // 0..1   tile col
    const int by = blockIdx.y;            // 0..63  tile row
    const int bc = blockIdx.z;            // 0..5   (b, c) fused
    const int b  = bc / CC;
    const int c  = bc - b * CC;
    const int x0 = bx * TILE_W;
    const int y0 = by * TILE_H;

    const int tid  = threadIdx.x;
    const int lane = tid & 31;
    const int wy   = tid >> 5;            // warp id == row within tile
    const int y    = y0 + wy;             // output row
    const int w0   = x0 + 4 * lane;       // first of 4 output cols

    const float* Hb = hor + ((size_t)b * KF * HW) + (size_t)y * WW + w0;
    const float* Vb = ver + ((size_t)b * KF * HW) + (size_t)y * WW + w0;

    // ---- single patch fill for this CTA's channel (+ zero pad cols) ----
    {
        const float* src = inp + ((size_t)(b * CC + c) * IN_H + y0) * IN_W + x0;
        for (int t = tid; t < PATCH_H * (PATCH_W / 2); t += NTHREADS) {
            int r  = t / (PATCH_W / 2);
            int c2 = t - r * (PATCH_W / 2);
            float2 v = *(const float2*)(src + (size_t)r * IN_W + 2 * c2);
            *(float2*)(&sm[r][2 * c2]) = v;
        }
        if (tid < PATCH_H) {              // pad cols read by the dead pair m=27
            sm[tid][PATCH_W]     = 0.0f;
            sm[tid][PATCH_W + 1] = 0.0f;
        }
    }
    __syncthreads();

    // per-thread shared base address: row wy (+i), float col 4*lane
    const uint32_t smbase = (uint32_t)__cvta_generic_to_shared(&sm[0][0])
                          + (uint32_t)(wy * ROW_BYTES) + (uint32_t)(lane * 16);

    // packed accumulators, carried across all 3 phases
    uint64_t o0 = 0, o1 = 0, o2 = 0, o3 = 0;

    // phases: m = 0..9, 10..19, 20..27 (byte bases 0 / 80 / 160)
    run_phase<0,  10>(Hb, Vb, smbase, o0, o1, o2, o3);
    __syncthreads();   // liveness fence: next phase's weights stay below
    run_phase<10, 10>(Hb, Vb, smbase, o0, o1, o2, o3);
    __syncthreads();
    run_phase<20,  8>(Hb, Vb, smbase, o0, o1, o2, o3);

    // ---- write out ----
    float* o = out + ((size_t)(b * CC + c) * HH + y) * WW + w0;
    *(float4*)o = make_float4(hadd2(o0), hadd2(o1), hadd2(o2), hadd2(o3));
}

extern "C" void kernel_launch(void* const* d_in, const int* in_sizes, int n_in,
                              void* d_out, int out_size)
{
    (void)in_sizes; (void)n_in; (void)out_size;
    const float* inp = (const float*)d_in[0];   // [B, C, 306, 306]
    const float* ver = (const float*)d_in[1];   // [B, 51, 256, 256]
    const float* hor = (const float*)d_in[2];   // [B, 51, 256, 256]
    float*       out = (float*)d_out;           // [B, C, 256, 256]

    dim3 grid(WW / TILE_W, HH / TILE_H, BB * CC);   // (2, 64, 6) = 768 blocks
    dim3 block(NTHREADS);
    sepconv_kernel<<<grid, block>>>(inp, ver, hor, out);
}